// round 1
// baseline (speedup 1.0000x reference)
#include <cuda_runtime.h>

#define BDIM 288
#define DISP 4
#define ND 9
#define CH 128
#define HH 96
#define WW 160
#define NB 8
#define TY 8
#define TX 32
#define CCH 8
#define FRS 36              // first tile row stride (floats), pad for bank spread
#define FCS (TY * FRS)      // 288 floats per channel plane (first)
#define SRS 44              // second tile row stride (floats)
#define SROWS (TY + 2 * DISP)   // 16 rows
#define SCS (SROWS * SRS)   // 704 floats per channel plane (second)

typedef unsigned long long u64;

static __device__ __forceinline__ u64 pk(float lo, float hi) {
    u64 r; asm("mov.b64 %0, {%1, %2};" : "=l"(r) : "f"(lo), "f"(hi)); return r;
}
static __device__ __forceinline__ void fma2(u64 &d, u64 a, u64 b) {
    asm("fma.rn.f32x2 %0, %1, %2, %0;" : "+l"(d) : "l"(a), "l"(b));
}
static __device__ __forceinline__ void unpk(u64 v, float &lo, float &hi) {
    asm("mov.b64 {%0, %1}, %2;" : "=f"(lo), "=f"(hi) : "l"(v));
}

__global__ __launch_bounds__(BDIM, 1)
void corr_kernel(const float* __restrict__ first,
                 const float* __restrict__ second,
                 float* __restrict__ out) {
    __shared__ __align__(16) float sF[CCH * FCS];   //  9216 B
    __shared__ __align__(16) float sS[CCH * SCS];   // 22528 B

    const int tid = threadIdx.x;
    const int b   = blockIdx.z;
    const int y0  = blockIdx.y * TY;
    const int x0  = blockIdx.x * TX;

    const int d    = tid >> 5;      // dy index 0..8 (warp id)
    const int lane = tid & 31;
    const int ty   = lane >> 2;     // 0..7
    const int xg   = lane & 3;      // 0..3 -> pixels 8*xg .. 8*xg+7

    u64 acc[36];                    // [pixel-pair i(0..3)][dx j(0..8)], packed f32x2
    #pragma unroll
    for (int i = 0; i < 36; i++) acc[i] = 0ull;

    for (int c0 = 0; c0 < CH; c0 += CCH) {
        __syncthreads();

        // ---- stage first tile: CCH x TY x TX floats = 512 float4 ----
        for (int id = tid; id < (CCH * TY * TX) / 4; id += BDIM) {
            int c  = id >> 6;          // /64 quads per channel
            int r  = (id >> 3) & 7;
            int xq = id & 7;
            const float4 v = *reinterpret_cast<const float4*>(
                &first[(((b * CH + c0 + c) * HH + y0 + r) * WW) + x0 + 4 * xq]);
            *reinterpret_cast<float4*>(&sF[c * FCS + r * FRS + 4 * xq]) = v;
        }

        // ---- stage second tile: CCH x 16 rows x 40 cols = 1280 quads ----
        for (int id = tid; id < CCH * SROWS * 10; id += BDIM) {
            int c   = id / (SROWS * 10);
            int rem = id - c * (SROWS * 10);
            int r   = rem / 10;
            int q   = rem - r * 10;
            int gy  = y0 - DISP + r;
            int gx  = x0 - DISP + 4 * q;
            float4 v = make_float4(0.f, 0.f, 0.f, 0.f);
            if ((unsigned)gy < HH) {
                if (gx >= 0 && gx + 3 < WW) {
                    v = *reinterpret_cast<const float4*>(
                        &second[(((b * CH + c0 + c) * HH + gy) * WW) + gx]);
                } else {
                    const float* base = &second[(((b * CH + c0 + c) * HH + gy) * WW)];
                    float t0 = ((unsigned)(gx + 0) < WW) ? base[gx + 0] : 0.f;
                    float t1 = ((unsigned)(gx + 1) < WW) ? base[gx + 1] : 0.f;
                    float t2 = ((unsigned)(gx + 2) < WW) ? base[gx + 2] : 0.f;
                    float t3 = ((unsigned)(gx + 3) < WW) ? base[gx + 3] : 0.f;
                    v = make_float4(t0, t1, t2, t3);
                }
            }
            *reinterpret_cast<float4*>(&sS[c * SCS + r * SRS + 4 * q]) = v;
        }
        __syncthreads();

        const float* fptr = &sF[ty * FRS + 8 * xg];
        const float* sptr = &sS[(ty + d) * SRS + 8 * xg];

        #pragma unroll
        for (int cc = 0; cc < CCH; cc++) {
            // first pixels as packed f32x2 pairs directly (128-bit LDS)
            const ulonglong2 fq0 = *reinterpret_cast<const ulonglong2*>(fptr + cc * FCS);
            const ulonglong2 fq1 = *reinterpret_cast<const ulonglong2*>(fptr + cc * FCS + 4);
            // second window: 16 floats
            const float4 s0 = *reinterpret_cast<const float4*>(sptr + cc * SCS);
            const float4 s1 = *reinterpret_cast<const float4*>(sptr + cc * SCS + 4);
            const float4 s2 = *reinterpret_cast<const float4*>(sptr + cc * SCS + 8);
            const float4 s3 = *reinterpret_cast<const float4*>(sptr + cc * SCS + 12);

            u64 P[15];  // P[k] = (s[k], s[k+1])
            P[0]  = pk(s0.x, s0.y);  P[1]  = pk(s0.y, s0.z);
            P[2]  = pk(s0.z, s0.w);  P[3]  = pk(s0.w, s1.x);
            P[4]  = pk(s1.x, s1.y);  P[5]  = pk(s1.y, s1.z);
            P[6]  = pk(s1.z, s1.w);  P[7]  = pk(s1.w, s2.x);
            P[8]  = pk(s2.x, s2.y);  P[9]  = pk(s2.y, s2.z);
            P[10] = pk(s2.z, s2.w);  P[11] = pk(s2.w, s3.x);
            P[12] = pk(s3.x, s3.y);  P[13] = pk(s3.y, s3.z);
            P[14] = pk(s3.z, s3.w);

            #pragma unroll
            for (int j = 0; j < ND; j++) {
                fma2(acc[j],      fq0.x, P[j]);
                fma2(acc[9 + j],  fq0.y, P[2 + j]);
                fma2(acc[18 + j], fq1.x, P[4 + j]);
                fma2(acc[27 + j], fq1.y, P[6 + j]);
            }
        }
    }

    // ---- epilogue: 81-channel output, chan = dy*9 + dx (dx fastest) ----
    const float inv_c = 1.0f / (float)CH;
    const int gy = y0 + ty;
    const int gx = x0 + 8 * xg;
    #pragma unroll
    for (int j = 0; j < ND; j++) {
        const int chan = d * ND + j;
        float* o = &out[(((b * 81 + chan) * HH + gy) * WW) + gx];
        float a0, a1, a2, a3, a4, a5, a6, a7;
        unpk(acc[j],      a0, a1);
        unpk(acc[9 + j],  a2, a3);
        unpk(acc[18 + j], a4, a5);
        unpk(acc[27 + j], a6, a7);
        float4 v0 = make_float4(a0 * inv_c, a1 * inv_c, a2 * inv_c, a3 * inv_c);
        float4 v1 = make_float4(a4 * inv_c, a5 * inv_c, a6 * inv_c, a7 * inv_c);
        *reinterpret_cast<float4*>(o)     = v0;
        *reinterpret_cast<float4*>(o + 4) = v1;
    }
}

extern "C" void kernel_launch(void* const* d_in, const int* in_sizes, int n_in,
                              void* d_out, int out_size) {
    const float* first  = (const float*)d_in[0];
    const float* second = (const float*)d_in[1];
    float* out = (float*)d_out;
    (void)in_sizes; (void)n_in; (void)out_size;

    dim3 grid(WW / TX, HH / TY, NB);   // (5, 12, 8)
    corr_kernel<<<grid, BDIM>>>(first, second, out);
}

// round 5
// speedup vs baseline: 1.9234x; 1.9234x over previous
#include <cuda_runtime.h>
#include <cstdint>

#define BDIM 288
#define DISP 4
#define ND 9
#define CH 128
#define HH 96
#define WW 160
#define NB 8
#define TY 8
#define TX 32
#define CCH 4
#define NSTAGE (CH / CCH)        // 32
#define FRS 36                   // first tile row stride (floats)
#define FCS (TY * FRS)           // 288 floats / channel
#define SRS 44                   // second tile row stride (floats)
#define SROWS (TY + 2 * DISP)    // 16
#define SCS (SROWS * SRS)        // 704 floats / channel

typedef unsigned long long u64;

static __device__ __forceinline__ u64 pk(float lo, float hi) {
    u64 r; asm("mov.b64 %0, {%1, %2};" : "=l"(r) : "f"(lo), "f"(hi)); return r;
}
static __device__ __forceinline__ void fma2(u64 &d, u64 a, u64 b) {
    asm("fma.rn.f32x2 %0, %1, %2, %0;" : "+l"(d) : "l"(a), "l"(b));
}
static __device__ __forceinline__ void unpk(u64 v, float &lo, float &hi) {
    asm("mov.b64 {%0, %1}, %2;" : "=f"(lo), "=f"(hi) : "l"(v));
}
static __device__ __forceinline__ void cpa16(uint32_t saddr, const void* gptr, int srcsz) {
    asm volatile("cp.async.cg.shared.global [%0], [%1], 16, %2;"
                 :: "r"(saddr), "l"(gptr), "r"(srcsz));
}
static __device__ __forceinline__ void cpa_commit() {
    asm volatile("cp.async.commit_group;");
}
template <int N> static __device__ __forceinline__ void cpa_wait() {
    asm volatile("cp.async.wait_group %0;" :: "n"(N));
}

__global__ __launch_bounds__(BDIM, 1)
void corr_kernel(const float* __restrict__ first,
                 const float* __restrict__ second,
                 float* __restrict__ out) {
    __shared__ __align__(16) float sF[2][CCH * FCS];   //  9216 B
    __shared__ __align__(16) float sS[2][CCH * SCS];   // 22528 B

    const int tid = threadIdx.x;
    const int b   = blockIdx.z;
    const int y0  = blockIdx.y * TY;
    const int x0  = blockIdx.x * TX;

    const int d    = tid >> 5;      // dy index 0..8 (warp id)
    const int lane = tid & 31;
    const int ty   = lane >> 2;     // 0..7
    const int xg   = lane & 3;      // 0..3 -> pixels 8*xg .. 8*xg+7

    u64 acc[36];
    #pragma unroll
    for (int i = 0; i < 36; i++) acc[i] = 0ull;

    // ---- staging lambda: issue cp.async for stage s into buffer bi ----
    auto stage = [&](int s, int bi) {
        const int c0 = s * CCH;
        const uint32_t sFb = (uint32_t)__cvta_generic_to_shared(&sF[bi][0]);
        const uint32_t sSb = (uint32_t)__cvta_generic_to_shared(&sS[bi][0]);

        // first: CCH x 8 rows x 8 quads = 256 quads (tid < 256 each does one)
        if (tid < CCH * TY * (TX / 4)) {
            int c  = tid >> 6;
            int r  = (tid >> 3) & 7;
            int xq = tid & 7;
            const float* g = &first[(((b * CH + c0 + c) * HH + y0 + r) * WW) + x0 + 4 * xq];
            cpa16(sFb + (c * FCS + r * FRS + 4 * xq) * 4, g, 16);
        }
        // second: CCH x 16 rows x 10 quads = 640 quads
        #pragma unroll 1
        for (int id = tid; id < CCH * SROWS * 10; id += BDIM) {
            int c   = id / (SROWS * 10);
            int rem = id - c * (SROWS * 10);
            int r   = rem / 10;
            int q   = rem - r * 10;
            int gy  = y0 - DISP + r;
            int gx  = x0 - DISP + 4 * q;
            // full-quad in/out property: gx multiple of 4, so quad is all-in or all-out
            bool ok = ((unsigned)gy < HH) && ((unsigned)gx <= (WW - 4));
            int cgy = ok ? gy : 0;
            int cgx = ok ? gx : 0;
            const float* g = &second[(((b * CH + c0 + c) * HH + cgy) * WW) + cgx];
            cpa16(sSb + (c * SCS + r * SRS + 4 * q) * 4, g, ok ? 16 : 0);
        }
    };

    stage(0, 0);
    cpa_commit();

    #pragma unroll 1
    for (int s = 0; s < NSTAGE; s++) {
        if (s + 1 < NSTAGE) {
            stage(s + 1, (s + 1) & 1);
            cpa_commit();
            cpa_wait<1>();
        } else {
            cpa_wait<0>();
        }
        __syncthreads();

        const int bi = s & 1;
        const float* fptr = &sF[bi][ty * FRS + 8 * xg];
        const float* sptr = &sS[bi][(ty + d) * SRS + 8 * xg];

        #pragma unroll
        for (int cc = 0; cc < CCH; cc++) {
            const ulonglong2 fq0 = *reinterpret_cast<const ulonglong2*>(fptr + cc * FCS);
            const ulonglong2 fq1 = *reinterpret_cast<const ulonglong2*>(fptr + cc * FCS + 4);
            const float4 s0 = *reinterpret_cast<const float4*>(sptr + cc * SCS);
            const float4 s1 = *reinterpret_cast<const float4*>(sptr + cc * SCS + 4);
            const float4 s2 = *reinterpret_cast<const float4*>(sptr + cc * SCS + 8);
            const float4 s3 = *reinterpret_cast<const float4*>(sptr + cc * SCS + 12);

            u64 P[15];
            P[0]  = pk(s0.x, s0.y);  P[1]  = pk(s0.y, s0.z);
            P[2]  = pk(s0.z, s0.w);  P[3]  = pk(s0.w, s1.x);
            P[4]  = pk(s1.x, s1.y);  P[5]  = pk(s1.y, s1.z);
            P[6]  = pk(s1.z, s1.w);  P[7]  = pk(s1.w, s2.x);
            P[8]  = pk(s2.x, s2.y);  P[9]  = pk(s2.y, s2.z);
            P[10] = pk(s2.z, s2.w);  P[11] = pk(s2.w, s3.x);
            P[12] = pk(s3.x, s3.y);  P[13] = pk(s3.y, s3.z);
            P[14] = pk(s3.z, s3.w);

            #pragma unroll
            for (int j = 0; j < ND; j++) {
                fma2(acc[j],      fq0.x, P[j]);
                fma2(acc[9 + j],  fq0.y, P[2 + j]);
                fma2(acc[18 + j], fq1.x, P[4 + j]);
                fma2(acc[27 + j], fq1.y, P[6 + j]);
            }
        }
        __syncthreads();
    }

    // ---- epilogue: chan = dy*9 + dx ----
    const float inv_c = 1.0f / (float)CH;
    const int gy = y0 + ty;
    const int gx = x0 + 8 * xg;
    #pragma unroll
    for (int j = 0; j < ND; j++) {
        const int chan = d * ND + j;
        float* o = &out[(((b * 81 + chan) * HH + gy) * WW) + gx];
        float a0, a1, a2, a3, a4, a5, a6, a7;
        unpk(acc[j],      a0, a1);
        unpk(acc[9 + j],  a2, a3);
        unpk(acc[18 + j], a4, a5);
        unpk(acc[27 + j], a6, a7);
        float4 v0 = make_float4(a0 * inv_c, a1 * inv_c, a2 * inv_c, a3 * inv_c);
        float4 v1 = make_float4(a4 * inv_c, a5 * inv_c, a6 * inv_c, a7 * inv_c);
        *reinterpret_cast<float4*>(o)     = v0;
        *reinterpret_cast<float4*>(o + 4) = v1;
    }
}

extern "C" void kernel_launch(void* const* d_in, const int* in_sizes, int n_in,
                              void* d_out, int out_size) {
    const float* first  = (const float*)d_in[0];
    const float* second = (const float*)d_in[1];
    float* out = (float*)d_out;
    (void)in_sizes; (void)n_in; (void)out_size;

    dim3 grid(WW / TX, HH / TY, NB);   // (5, 12, 8)
    corr_kernel<<<grid, BDIM>>>(first, second, out);
}

// round 6
// speedup vs baseline: 2.2186x; 1.1535x over previous
#include <cuda_runtime.h>
#include <cstdint>

#define BDIM 288
#define DISP 4
#define ND 9
#define CH 128
#define HH 96
#define WW 160
#define NB 8
#define TY 8
#define TX 32
#define CCH 4
#define NBUF 3
#define NSTAGE (CH / CCH)        // 32
#define FRS 36                   // first tile row stride (floats)
#define FCS (TY * FRS)           // 288 floats / channel
#define SRS 44                   // second tile row stride (floats)
#define SROWS (TY + 2 * DISP)    // 16
#define SCS (SROWS * SRS)        // 704 floats / channel
#define CHSTRIDE (HH * WW)       // floats per channel plane

typedef unsigned long long u64;

struct F2 { float lo, hi; };

static __device__ __forceinline__ u64 pk(float lo, float hi) {
    u64 r; asm("mov.b64 %0, {%1, %2};" : "=l"(r) : "f"(lo), "f"(hi)); return r;
}
static __device__ __forceinline__ F2 unp(u64 v) {
    F2 r; asm("mov.b64 {%0, %1}, %2;" : "=f"(r.lo), "=f"(r.hi) : "l"(v)); return r;
}
static __device__ __forceinline__ void fma2(u64 &d, u64 a, u64 b) {
    asm("fma.rn.f32x2 %0, %1, %2, %0;" : "+l"(d) : "l"(a), "l"(b));
}
static __device__ __forceinline__ void cpa16(uint32_t saddr, const void* gptr, int srcsz) {
    asm volatile("cp.async.cg.shared.global [%0], [%1], 16, %2;"
                 :: "r"(saddr), "l"(gptr), "r"(srcsz));
}
static __device__ __forceinline__ void cpa_commit() {
    asm volatile("cp.async.commit_group;");
}
template <int N> static __device__ __forceinline__ void cpa_wait() {
    asm volatile("cp.async.wait_group %0;" :: "n"(N));
}

__global__ __launch_bounds__(BDIM, 1)
void corr_kernel(const float* __restrict__ first,
                 const float* __restrict__ second,
                 float* __restrict__ out) {
    __shared__ __align__(16) float sF[NBUF][CCH * FCS];   // 13.8 KB
    __shared__ __align__(16) float sS[NBUF][CCH * SCS];   // 33.8 KB

    const int tid = threadIdx.x;
    const int b   = blockIdx.z;
    const int y0  = blockIdx.y * TY;
    const int x0  = blockIdx.x * TX;

    const int d    = tid >> 5;      // dy index 0..8 (warp id)
    const int lane = tid & 31;
    const int ty   = lane >> 2;     // 0..7
    const int xg   = lane & 3;      // 0..3 -> pixels 8*xg .. 8*xg+7

    const uint32_t sF0 = (uint32_t)__cvta_generic_to_shared(&sF[0][0]);
    const uint32_t sS0 = (uint32_t)__cvta_generic_to_shared(&sS[0][0]);

    // ---- persistent staging assignments (computed once) ----
    // threads 0..159: one fixed (r,q) position of the second tile, loop over c
    // threads 160..287: two fixed quads of the first tile, loop over stages
    const float* g2base = nullptr;  uint32_t soff2 = 0;  int ok2 = 0;
    const float* g1base0 = nullptr; const float* g1base1 = nullptr;
    uint32_t soff1_0 = 0, soff1_1 = 0;

    if (tid < 160) {
        const int r2 = tid / 10;
        const int q2 = tid - r2 * 10;
        const int gy = y0 - DISP + r2;
        const int gx = x0 - DISP + 4 * q2;
        ok2 = (((unsigned)gy < HH) && ((unsigned)gx <= (WW - 4))) ? 16 : 0;
        const int cgy = ok2 ? gy : 0;
        const int cgx = ok2 ? gx : 0;
        g2base = second + ((size_t)b * CH * HH + cgy) * WW + cgx;
        soff2 = (uint32_t)(r2 * SRS + 4 * q2) * 4u;
    } else {
        const int i = tid - 160;
        #pragma unroll
        for (int k = 0; k < 2; k++) {
            const int qid = 2 * i + k;
            const int ca  = qid >> 6;
            const int p   = qid & 63;
            const int ra  = p >> 3;
            const int xqa = p & 7;
            const float* g = first + ((size_t)(b * CH + ca) * HH + y0 + ra) * WW + x0 + 4 * xqa;
            const uint32_t so = (uint32_t)(ca * FCS + ra * FRS + 4 * xqa) * 4u;
            if (k == 0) { g1base0 = g; soff1_0 = so; } else { g1base1 = g; soff1_1 = so; }
        }
    }

    auto stage = [&](int s, int bi) {
        if (tid < 160) {
            const uint32_t sSb = sS0 + (uint32_t)(bi * CCH * SCS) * 4u + soff2;
            const float* g = g2base + (size_t)(s * CCH) * CHSTRIDE;
            #pragma unroll
            for (int c = 0; c < CCH; c++)
                cpa16(sSb + (uint32_t)(c * SCS) * 4u, g + (size_t)c * CHSTRIDE, ok2);
        } else {
            const uint32_t sFb = sF0 + (uint32_t)(bi * CCH * FCS) * 4u;
            const size_t off = (size_t)(s * CCH) * CHSTRIDE;
            cpa16(sFb + soff1_0, g1base0 + off, 16);
            cpa16(sFb + soff1_1, g1base1 + off, 16);
        }
    };

    u64 acc[36];
    #pragma unroll
    for (int i = 0; i < 36; i++) acc[i] = 0ull;

    stage(0, 0); cpa_commit();
    stage(1, 1); cpa_commit();

    int bR = 0;      // buffer being computed
    int bW = 2;      // buffer being staged (s+2)

    #pragma unroll 1
    for (int s = 0; s < NSTAGE; s++) {
        if (s + 2 < NSTAGE) {
            cpa_wait<1>();
            __syncthreads();
            stage(s + 2, bW);
            cpa_commit();
        } else if (s + 1 < NSTAGE) {
            cpa_wait<1>();
            __syncthreads();
        } else {
            cpa_wait<0>();
            __syncthreads();
        }

        const float* fptr = &sF[bR][ty * FRS + 8 * xg];
        const float* sptr = &sS[bR][(ty + d) * SRS + 8 * xg];

        #pragma unroll
        for (int cc = 0; cc < CCH; cc++) {
            const ulonglong2 F01 = *reinterpret_cast<const ulonglong2*>(fptr + cc * FCS);
            const ulonglong2 F23 = *reinterpret_cast<const ulonglong2*>(fptr + cc * FCS + 4);
            const ulonglong2 E01 = *reinterpret_cast<const ulonglong2*>(sptr + cc * SCS);
            const ulonglong2 E23 = *reinterpret_cast<const ulonglong2*>(sptr + cc * SCS + 4);
            const ulonglong2 E45 = *reinterpret_cast<const ulonglong2*>(sptr + cc * SCS + 8);
            const ulonglong2 E67 = *reinterpret_cast<const ulonglong2*>(sptr + cc * SCS + 12);

            const F2 a0 = unp(E01.x), a1 = unp(E01.y);
            const F2 a2 = unp(E23.x), a3 = unp(E23.y);
            const F2 a4 = unp(E45.x), a5 = unp(E45.y);
            const F2 a6 = unp(E67.x), a7 = unp(E67.y);

            u64 P[15];
            P[0]  = E01.x;            P[2]  = E01.y;
            P[4]  = E23.x;            P[6]  = E23.y;
            P[8]  = E45.x;            P[10] = E45.y;
            P[12] = E67.x;            P[14] = E67.y;
            P[1]  = pk(a0.hi, a1.lo); P[3]  = pk(a1.hi, a2.lo);
            P[5]  = pk(a2.hi, a3.lo); P[7]  = pk(a3.hi, a4.lo);
            P[9]  = pk(a4.hi, a5.lo); P[11] = pk(a5.hi, a6.lo);
            P[13] = pk(a6.hi, a7.lo);

            #pragma unroll
            for (int j = 0; j < ND; j++) {
                fma2(acc[j],      F01.x, P[j]);
                fma2(acc[9 + j],  F01.y, P[2 + j]);
                fma2(acc[18 + j], F23.x, P[4 + j]);
                fma2(acc[27 + j], F23.y, P[6 + j]);
            }
        }

        if (++bR == NBUF) bR = 0;
        if (++bW == NBUF) bW = 0;
    }

    // ---- epilogue: chan = dy*9 + dx (dx fastest) ----
    const float inv_c = 1.0f / (float)CH;
    const int gy = y0 + ty;
    const int gx = x0 + 8 * xg;
    #pragma unroll
    for (int j = 0; j < ND; j++) {
        const int chan = d * ND + j;
        float* o = &out[(((b * 81 + chan) * HH + gy) * WW) + gx];
        const F2 r0 = unp(acc[j]);
        const F2 r1 = unp(acc[9 + j]);
        const F2 r2 = unp(acc[18 + j]);
        const F2 r3 = unp(acc[27 + j]);
        float4 v0 = make_float4(r0.lo * inv_c, r0.hi * inv_c, r1.lo * inv_c, r1.hi * inv_c);
        float4 v1 = make_float4(r2.lo * inv_c, r2.hi * inv_c, r3.lo * inv_c, r3.hi * inv_c);
        *reinterpret_cast<float4*>(o)     = v0;
        *reinterpret_cast<float4*>(o + 4) = v1;
    }
}

extern "C" void kernel_launch(void* const* d_in, const int* in_sizes, int n_in,
                              void* d_out, int out_size) {
    const float* first  = (const float*)d_in[0];
    const float* second = (const float*)d_in[1];
    float* out = (float*)d_out;
    (void)in_sizes; (void)n_in; (void)out_size;

    dim3 grid(WW / TX, HH / TY, NB);   // (5, 12, 8)
    corr_kernel<<<grid, BDIM>>>(first, second, out);
}